// round 3
// baseline (speedup 1.0000x reference)
#include <cuda_runtime.h>
#include <math.h>

// Problem constants
#define Bn   8
#define Cc   192
#define Hh   56
#define Ww   56
#define Nn   3136          // H*W
#define Kk   9
#define C2c  384           // 2*C
#define OUTc 192
#define Mrows 25088        // B*N
#define EPSf 1e-5f

// ------------------------- device scratch (no mallocs allowed) -------------
__device__ float  g_xt[Bn * Nn * Cc];          // [B,N,C]   19.3 MB
__device__ float  g_w1t[C2c * C2c];            // w1^T [c][o]
__device__ float  g_w2t[C2c * OUTc];           // w2^T [c][o]
__device__ float  g_feats[(size_t)Mrows * C2c];// [M,384]   38.5 MB
__device__ float  g_h1[(size_t)Mrows * C2c];   // [M,384]   38.5 MB
__device__ float  g_h2[(size_t)Mrows * OUTc];  // [M,192]   19.3 MB
__device__ float  g_ps[128 * C2c];             // stat partial sums
__device__ float  g_pq[128 * C2c];             // stat partial sumsq
__device__ float2 g_aff1[C2c];                 // (scale, shift) for BN1
__device__ float2 g_aff2[OUTc];                // (scale, shift) for BN2

__device__ __forceinline__ float gelu_exact(float x) {
    return 0.5f * x * (1.0f + erff(x * 0.70710678118654752f));
}

// ------------------------- transposes --------------------------------------
// x[b][c][n] -> xt[b][n][c]
__global__ void transpose_x_kernel(const float* __restrict__ x, float* __restrict__ xt) {
    __shared__ float tile[32][33];
    int b  = blockIdx.z;
    int n0 = blockIdx.x * 32;
    int c0 = blockIdx.y * 32;
    int tx = threadIdx.x, ty = threadIdx.y;
    tile[ty][tx] = x[((size_t)b * Cc + c0 + ty) * Nn + n0 + tx];
    __syncthreads();
    xt[((size_t)b * Nn + n0 + ty) * Cc + c0 + tx] = tile[tx][ty];
}

// w[o][c] -> wt[c][o]   (rows = #o, cols = #c; both multiples of 32)
__global__ void transpose_w_kernel(const float* __restrict__ w, float* __restrict__ wt,
                                   int rows, int cols) {
    __shared__ float tile[32][33];
    int c0 = blockIdx.x * 32;
    int o0 = blockIdx.y * 32;
    int tx = threadIdx.x, ty = threadIdx.y;
    tile[ty][tx] = w[(size_t)(o0 + ty) * cols + c0 + tx];
    __syncthreads();
    wt[(size_t)(c0 + ty) * rows + o0 + tx] = tile[tx][ty];
}

// ------------------------- gather + diff-max + interleave ------------------
// One warp per (b, n). feats[p][2c] = xt[p][c], feats[p][2c+1] = max_k(xj-xi)[c]
__global__ void __launch_bounds__(256)
gather_kernel(const float* __restrict__ xt, const int* __restrict__ edge,
              float* __restrict__ feats) {
    int warp = (blockIdx.x * blockDim.x + threadIdx.x) >> 5;   // 0..25087
    int lane = threadIdx.x & 31;
    int b = warp / Nn;
    int n = warp % Nn;
    const float* xb = xt + (size_t)b * Nn * Cc;

    float xv[6], mv[6];
#pragma unroll
    for (int j = 0; j < 6; j++) {
        xv[j] = xb[(size_t)n * Cc + lane + 32 * j];
        mv[j] = -3.402823466e38f;
    }

    const int* e0 = edge + ((size_t)b * Nn + n) * Kk;              // edge_idx[0]
    const int* e1 = e0 + (size_t)Bn * Nn * Kk;                     // edge_idx[1]
#pragma unroll
    for (int k = 0; k < Kk; k++) {
        int jn  = __ldg(&e0[k]);
        int in_ = __ldg(&e1[k]);
        const float* rj = xb + (size_t)jn  * Cc;
        const float* ri = xb + (size_t)in_ * Cc;
#pragma unroll
        for (int j = 0; j < 6; j++) {
            int c = lane + 32 * j;
            mv[j] = fmaxf(mv[j], __ldg(&rj[c]) - __ldg(&ri[c]));
        }
    }

    float2* fo = reinterpret_cast<float2*>(feats + (size_t)warp * C2c);
#pragma unroll
    for (int j = 0; j < 6; j++)
        fo[lane + 32 * j] = make_float2(xv[j], mv[j]);
}

// ------------------------- tiled fp32 GEMM ---------------------------------
// C[M,N] = op(A)[M,K] * Bt[K,N] + bias[N]
// op(A) = A                       if !PRE
// op(A) = gelu(A*scale[k]+shift)  if PRE  (per-K-column affine, i.e. fused BN1+GELU)
// All dims exactly divide tiles; no bounds checks.
template <int BM, int BN, int BK, int TM, int TN, bool PRE>
__global__ void __launch_bounds__(256, 2)
gemm_kernel(const float* __restrict__ A, const float* __restrict__ Bt,
            const float* __restrict__ bias, const float2* __restrict__ pre,
            float* __restrict__ Cout, int Mdim, int Ndim, int Kdim) {
    __shared__ float As[BK][BM];
    __shared__ float Bs[BK][BN];
    constexpr int TX    = BN / TN;         // 16
    constexpr int KG    = BK / 4;          // float4 groups along K in A tile
    constexpr int A_PER = (BM * BK / 4) / 256;
    constexpr int BC    = BN / 4;
    constexpr int B_PER = (BK * BN / 4) / 256;

    const int tid = threadIdx.x;
    const int tx  = tid % TX;
    const int ty  = tid / TX;
    const int m0  = blockIdx.y * BM;
    const int n0  = blockIdx.x * BN;

    float acc[TM][TN];
#pragma unroll
    for (int i = 0; i < TM; i++)
#pragma unroll
        for (int j = 0; j < TN; j++) acc[i][j] = 0.0f;

    for (int kb = 0; kb < Kdim; kb += BK) {
        // A tile load (coalesced float4 along K), transpose into As[k][m]
#pragma unroll
        for (int i = 0; i < A_PER; i++) {
            int f  = tid + 256 * i;
            int ar = f / KG;
            int kg = f % KG;
            float4 v = *reinterpret_cast<const float4*>(
                &A[(size_t)(m0 + ar) * Kdim + kb + 4 * kg]);
            if (PRE) {
                const float2* pp = pre + kb + 4 * kg;
                float2 s0 = pp[0], s1 = pp[1], s2 = pp[2], s3 = pp[3];
                v.x = gelu_exact(fmaf(v.x, s0.x, s0.y));
                v.y = gelu_exact(fmaf(v.y, s1.x, s1.y));
                v.z = gelu_exact(fmaf(v.z, s2.x, s2.y));
                v.w = gelu_exact(fmaf(v.w, s3.x, s3.y));
            }
            As[4 * kg + 0][ar] = v.x;
            As[4 * kg + 1][ar] = v.y;
            As[4 * kg + 2][ar] = v.z;
            As[4 * kg + 3][ar] = v.w;
        }
        // B tile load (coalesced float4 along N)
#pragma unroll
        for (int i = 0; i < B_PER; i++) {
            int f  = tid + 256 * i;
            int br = f / BC;
            int bc = f % BC;
            float4 v = *reinterpret_cast<const float4*>(
                &Bt[(size_t)(kb + br) * Ndim + n0 + 4 * bc]);
            *reinterpret_cast<float4*>(&Bs[br][4 * bc]) = v;
        }
        __syncthreads();

#pragma unroll
        for (int k = 0; k < BK; k++) {
            float a[TM], bb[TN];
#pragma unroll
            for (int i = 0; i < TM; i += 4)
                *reinterpret_cast<float4*>(&a[i]) =
                    *reinterpret_cast<const float4*>(&As[k][ty * TM + i]);
#pragma unroll
            for (int j = 0; j < TN; j += 4)
                *reinterpret_cast<float4*>(&bb[j]) =
                    *reinterpret_cast<const float4*>(&Bs[k][tx * TN + j]);
#pragma unroll
            for (int i = 0; i < TM; i++)
#pragma unroll
                for (int j = 0; j < TN; j++)
                    acc[i][j] = fmaf(a[i], bb[j], acc[i][j]);
        }
        __syncthreads();
    }

    // epilogue: add bias, store
#pragma unroll
    for (int i = 0; i < TM; i++) {
        int row = m0 + ty * TM + i;
#pragma unroll
        for (int j = 0; j < TN; j += 4) {
            int col = n0 + tx * TN + j;
            float4 v;
            v.x = acc[i][j + 0] + bias[col + 0];
            v.y = acc[i][j + 1] + bias[col + 1];
            v.z = acc[i][j + 2] + bias[col + 2];
            v.w = acc[i][j + 3] + bias[col + 3];
            *reinterpret_cast<float4*>(&Cout[(size_t)row * Ndim + col]) = v;
        }
    }
}

// ------------------------- deterministic BN batch stats --------------------
// 128 blocks, each sums a fixed 196-row slab per channel. threads = ncols.
__global__ void stats_partial_kernel(const float* __restrict__ H, int ncols,
                                     int rowsPerBlk,
                                     float* __restrict__ ps, float* __restrict__ pq) {
    int c = threadIdx.x;
    size_t base = (size_t)blockIdx.x * rowsPerBlk;
    float s = 0.0f, q = 0.0f;
    for (int i = 0; i < rowsPerBlk; i++) {
        float v = H[(base + i) * ncols + c];
        s += v;
        q = fmaf(v, v, q);
    }
    ps[blockIdx.x * ncols + c] = s;
    pq[blockIdx.x * ncols + c] = q;
}

// 1 block, threads = ncols. Fixed-order reduce of 128 partials -> (scale,shift)
__global__ void stats_finalize_kernel(const float* __restrict__ ps,
                                      const float* __restrict__ pq, int ncols,
                                      const float* __restrict__ gamma,
                                      const float* __restrict__ beta,
                                      float2* __restrict__ aff) {
    int c = threadIdx.x;
    float s = 0.0f, q = 0.0f;
    for (int i = 0; i < 128; i++) {
        s += ps[i * ncols + c];
        q += pq[i * ncols + c];
    }
    const float inv = 1.0f / (float)Mrows;
    float mean = s * inv;
    float var  = q * inv - mean * mean;           // biased (jnp.var default)
    float sc   = gamma[c] * rsqrtf(var + EPSf);
    aff[c] = make_float2(sc, beta[c] - mean * sc);
}

// ------------------------- final BN+GELU + NHWC->NCHW ----------------------
__global__ void epilogue_kernel(const float* __restrict__ h2,
                                const float2* __restrict__ aff,
                                float* __restrict__ out) {
    __shared__ float tile[32][33];
    int b  = blockIdx.z;
    int n0 = blockIdx.x * 32;
    int o0 = blockIdx.y * 32;
    int tx = threadIdx.x, ty = threadIdx.y;
    float v  = h2[((size_t)b * Nn + n0 + ty) * OUTc + o0 + tx];
    float2 a = aff[o0 + tx];
    tile[ty][tx] = gelu_exact(fmaf(v, a.x, a.y));
    __syncthreads();
    out[((size_t)b * OUTc + o0 + ty) * Nn + n0 + tx] = tile[tx][ty];
}

// ------------------------- host driver -------------------------------------
extern "C" void kernel_launch(void* const* d_in, const int* in_sizes, int n_in,
                              void* d_out, int out_size) {
    const float* x    = (const float*)d_in[0];
    const int*   edge = (const int*)  d_in[1];
    const float* w1   = (const float*)d_in[2];
    const float* b1   = (const float*)d_in[3];
    const float* g1   = (const float*)d_in[4];
    const float* be1  = (const float*)d_in[5];
    const float* w2   = (const float*)d_in[6];
    const float* b2   = (const float*)d_in[7];
    const float* g2   = (const float*)d_in[8];
    const float* be2  = (const float*)d_in[9];
    float* out = (float*)d_out;

    float *xt, *w1t, *w2t, *feats, *h1, *h2, *ps, *pq;
    float2 *aff1, *aff2;
    cudaGetSymbolAddress((void**)&xt,    g_xt);
    cudaGetSymbolAddress((void**)&w1t,   g_w1t);
    cudaGetSymbolAddress((void**)&w2t,   g_w2t);
    cudaGetSymbolAddress((void**)&feats, g_feats);
    cudaGetSymbolAddress((void**)&h1,    g_h1);
    cudaGetSymbolAddress((void**)&h2,    g_h2);
    cudaGetSymbolAddress((void**)&ps,    g_ps);
    cudaGetSymbolAddress((void**)&pq,    g_pq);
    cudaGetSymbolAddress((void**)&aff1,  g_aff1);
    cudaGetSymbolAddress((void**)&aff2,  g_aff2);

    dim3 blk32(32, 32);

    // 1) layout prep
    transpose_x_kernel<<<dim3(Nn / 32, Cc / 32, Bn), blk32>>>(x, xt);
    transpose_w_kernel<<<dim3(C2c / 32, C2c / 32), blk32>>>(w1, w1t, C2c, C2c);
    transpose_w_kernel<<<dim3(C2c / 32, OUTc / 32), blk32>>>(w2, w2t, OUTc, C2c);

    // 2) gather + diff-max + interleave  (1 warp per point)
    gather_kernel<<<Mrows / 8, 256>>>(xt, edge, feats);

    // 3) GEMM1: [25088,384] x [384,384] + b1
    gemm_kernel<128, 128, 16, 8, 8, false>
        <<<dim3(C2c / 128, Mrows / 128), 256>>>(feats, w1t, b1, nullptr, h1,
                                                Mrows, C2c, C2c);

    // 4) BN1 stats (deterministic)
    stats_partial_kernel<<<128, C2c>>>(h1, C2c, Mrows / 128, ps, pq);
    stats_finalize_kernel<<<1, C2c>>>(ps, pq, C2c, g1, be1, aff1);

    // 5) GEMM2 with fused BN1+GELU on A-load: [25088,384] x [384,192] + b2
    gemm_kernel<128, 64, 16, 8, 4, true>
        <<<dim3(OUTc / 64, Mrows / 128), 256>>>(h1, w2t, b2, aff1, h2,
                                                Mrows, OUTc, C2c);

    // 6) BN2 stats (deterministic)
    stats_partial_kernel<<<128, OUTc>>>(h2, OUTc, Mrows / 128, ps, pq);
    stats_finalize_kernel<<<1, OUTc>>>(ps, pq, OUTc, g2, be2, aff2);

    // 7) final BN+GELU + transpose to [B, OUT, H, W]
    epilogue_kernel<<<dim3(Nn / 32, OUTc / 32, Bn), blk32>>>(h2, aff2, out);
}

// round 6
// speedup vs baseline: 1.5287x; 1.5287x over previous
#include <cuda_runtime.h>
#include <cuda_bf16.h>
#include <cstdint>
#include <math.h>

// Problem constants
#define Bn   8
#define Cc   192
#define Nn   3136          // H*W
#define Kk   9
#define C2c  384           // 2*C
#define OUTc 192
#define Mrows 25088        // B*N
#define EPSf 1e-5f
#define PARTS 256          // stats partial blocks (25088/256 = 98 rows each)

// ------------------------- device scratch ----------------------------------
__device__ __align__(16) float          g_xt[Bn * Nn * Cc];
__device__ __align__(16) __nv_bfloat16  g_a1hi[(size_t)Mrows * C2c];
__device__ __align__(16) __nv_bfloat16  g_a1lo[(size_t)Mrows * C2c];
__device__ __align__(16) __nv_bfloat16  g_a2hi[(size_t)Mrows * C2c];
__device__ __align__(16) __nv_bfloat16  g_a2lo[(size_t)Mrows * C2c];
__device__ __align__(16) __nv_bfloat16  g_w1hi[C2c * C2c];
__device__ __align__(16) __nv_bfloat16  g_w1lo[C2c * C2c];
__device__ __align__(16) __nv_bfloat16  g_w2hi[OUTc * C2c];
__device__ __align__(16) __nv_bfloat16  g_w2lo[OUTc * C2c];
__device__ __align__(16) float          g_h1[(size_t)Mrows * C2c];
__device__ __align__(16) float          g_h2[(size_t)Mrows * OUTc];
__device__ float  g_ps[PARTS * C2c];
__device__ float  g_pq[PARTS * C2c];
__device__ float2 g_aff1[C2c];
__device__ float2 g_aff2[OUTc];

__device__ __forceinline__ float gelu_exact(float x) {
    return 0.5f * x * (1.0f + erff(x * 0.70710678118654752f));
}
__device__ __forceinline__ void split_bf16(float v, __nv_bfloat16& hi, __nv_bfloat16& lo) {
    hi = __float2bfloat16(v);
    lo = __float2bfloat16(v - __bfloat162float(hi));
}
__device__ __forceinline__ uint32_t smem_u32(const void* p) {
    return (uint32_t)__cvta_generic_to_shared(p);
}
__device__ __forceinline__ void ldsm_x4(uint32_t* r, uint32_t addr) {
    asm volatile("ldmatrix.sync.aligned.m8n8.x4.shared.b16 {%0,%1,%2,%3}, [%4];"
                 : "=r"(r[0]), "=r"(r[1]), "=r"(r[2]), "=r"(r[3]) : "r"(addr));
}
__device__ __forceinline__ void mma16816(float* c, const uint32_t* a, const uint32_t* b) {
    asm volatile(
        "mma.sync.aligned.m16n8k16.row.col.f32.bf16.bf16.f32 "
        "{%0,%1,%2,%3}, {%4,%5,%6,%7}, {%8,%9}, {%0,%1,%2,%3};"
        : "+f"(c[0]), "+f"(c[1]), "+f"(c[2]), "+f"(c[3])
        : "r"(a[0]), "r"(a[1]), "r"(a[2]), "r"(a[3]), "r"(b[0]), "r"(b[1]));
}

// ------------------------- transpose x -------------------------------------
__global__ void transpose_x_kernel(const float* __restrict__ x, float* __restrict__ xt) {
    __shared__ float tile[32][33];
    int b  = blockIdx.z;
    int n0 = blockIdx.x * 32;
    int c0 = blockIdx.y * 32;
    int tx = threadIdx.x, ty = threadIdx.y;
    tile[ty][tx] = x[((size_t)b * Cc + c0 + ty) * Nn + n0 + tx];
    __syncthreads();
    xt[((size_t)b * Nn + n0 + ty) * Cc + c0 + tx] = tile[tx][ty];
}

// ------------------------- weight split ------------------------------------
__global__ void split_w_kernel(const float* __restrict__ w, __nv_bfloat16* __restrict__ hi,
                               __nv_bfloat16* __restrict__ lo, int n) {
    int i = blockIdx.x * 256 + threadIdx.x;
    if (i < n) split_bf16(w[i], hi[i], lo[i]);
}

// ------------------------- gather + diff-max + interleave + split ----------
__global__ void __launch_bounds__(256)
gather_kernel(const float* __restrict__ xt, const int* __restrict__ edge,
              __nv_bfloat16* __restrict__ ahi, __nv_bfloat16* __restrict__ alo) {
    int warp = (blockIdx.x * blockDim.x + threadIdx.x) >> 5;   // 0..25087
    int lane = threadIdx.x & 31;
    int b = warp / Nn;
    int n = warp % Nn;
    const float* xb = xt + (size_t)b * Nn * Cc;

    float xv[6], mv[6];
#pragma unroll
    for (int j = 0; j < 6; j++) {
        xv[j] = xb[(size_t)n * Cc + lane + 32 * j];
        mv[j] = -3.402823466e38f;
    }
    const int* e0 = edge + ((size_t)b * Nn + n) * Kk;
    const int* e1 = e0 + (size_t)Bn * Nn * Kk;
#pragma unroll
    for (int k = 0; k < Kk; k++) {
        int jn  = __ldg(&e0[k]);
        int in_ = __ldg(&e1[k]);
        const float* rj = xb + (size_t)jn  * Cc;
        const float* ri = xb + (size_t)in_ * Cc;
#pragma unroll
        for (int j = 0; j < 6; j++) {
            int c = lane + 32 * j;
            mv[j] = fmaxf(mv[j], __ldg(&rj[c]) - __ldg(&ri[c]));
        }
    }
    __nv_bfloat162* oh = reinterpret_cast<__nv_bfloat162*>(ahi + (size_t)warp * C2c);
    __nv_bfloat162* ol = reinterpret_cast<__nv_bfloat162*>(alo + (size_t)warp * C2c);
#pragma unroll
    for (int j = 0; j < 6; j++) {
        __nv_bfloat16 xh, xl, mh, ml;
        split_bf16(xv[j], xh, xl);
        split_bf16(mv[j], mh, ml);
        __nv_bfloat162 vh; vh.x = xh; vh.y = mh;
        __nv_bfloat162 vl; vl.x = xl; vl.y = ml;
        oh[lane + 32 * j] = vh;
        ol[lane + 32 * j] = vl;
    }
}

// ------------------------- mma.sync split-bf16 GEMM ------------------------
// C[M,Ndim] = A[M,384] * B[Ndim,384]^T + bias, 3-term bf16 split.
// BM=128, BN=64, BK=32. 8 warps (4x2), warp tile 32x32 (2x m16, 4x n8).
#define GBM 128
#define GBN 64
#define GBK 32
#define APAD 8      // bf16 pad per row
#define LDA (GBK + APAD)

__global__ void __launch_bounds__(256, 2)
mma_gemm_kernel(const __nv_bfloat16* __restrict__ Ahi, const __nv_bfloat16* __restrict__ Alo,
                const __nv_bfloat16* __restrict__ Bhi, const __nv_bfloat16* __restrict__ Blo,
                const float* __restrict__ bias, float* __restrict__ Cout, int Ndim) {
    __shared__ __nv_bfloat16 As[2][GBM][LDA];   // [hi/lo][row][k]
    __shared__ __nv_bfloat16 Bs[2][GBN][LDA];

    const int tid  = threadIdx.x;
    const int wid  = tid >> 5;
    const int lane = tid & 31;
    const int wm   = wid >> 1;          // 0..3
    const int wn   = wid & 1;           // 0..1
    const int m0   = blockIdx.y * GBM;
    const int n0   = blockIdx.x * GBN;

    float acc[2][4][4];
#pragma unroll
    for (int i = 0; i < 2; i++)
#pragma unroll
        for (int j = 0; j < 4; j++)
#pragma unroll
            for (int q = 0; q < 4; q++) acc[i][j][q] = 0.0f;

    // ldmatrix source coords (within warp tile)
    const int ar = lane & 15;               // A row within m16 tile
    const int ac = (lane >> 4) << 3;        // A k offset 0/8
    const int br = (lane & 7) + ((lane >> 4) << 3);   // B n row (0..15 within pair)
    const int bc = ((lane >> 3) & 1) << 3;            // B k offset 0/8

    for (int kb = 0; kb < C2c; kb += GBK) {
        // ---- load A tile (128x32, hi+lo): 2 uint4 per thread per buffer ----
#pragma unroll
        for (int i = 0; i < 2; i++) {
            int f = tid + 256 * i;
            int row = f >> 2, c8 = (f & 3) << 3;
            const size_t go = (size_t)(m0 + row) * C2c + kb + c8;
            uint4 vh = *reinterpret_cast<const uint4*>(Ahi + go);
            uint4 vl = *reinterpret_cast<const uint4*>(Alo + go);
            *reinterpret_cast<uint4*>(&As[0][row][c8]) = vh;
            *reinterpret_cast<uint4*>(&As[1][row][c8]) = vl;
        }
        // ---- load B tile (64x32, hi+lo): 1 uint4 per thread per buffer ----
        {
            int row = tid >> 2, c8 = (tid & 3) << 3;
            const size_t go = (size_t)(n0 + row) * C2c + kb + c8;
            uint4 vh = *reinterpret_cast<const uint4*>(Bhi + go);
            uint4 vl = *reinterpret_cast<const uint4*>(Blo + go);
            *reinterpret_cast<uint4*>(&Bs[0][row][c8]) = vh;
            *reinterpret_cast<uint4*>(&Bs[1][row][c8]) = vl;
        }
        __syncthreads();

#pragma unroll
        for (int ks = 0; ks < 2; ks++) {          // two k16 steps
            const int k16 = ks * 16;
            uint32_t ah[2][4], al[2][4];
#pragma unroll
            for (int mt = 0; mt < 2; mt++) {
                int row = wm * 32 + mt * 16 + ar;
                ldsm_x4(ah[mt], smem_u32(&As[0][row][k16 + ac]));
                ldsm_x4(al[mt], smem_u32(&As[1][row][k16 + ac]));
            }
            uint32_t bh[4][2], bl[4][2];
#pragma unroll
            for (int p = 0; p < 2; p++) {         // pairs of n8 tiles
                int row = wn * 32 + p * 16 + br;
                uint32_t t[4];
                ldsm_x4(t, smem_u32(&Bs[0][row][k16 + bc]));
                bh[2 * p][0] = t[0]; bh[2 * p][1] = t[1];
                bh[2 * p + 1][0] = t[2]; bh[2 * p + 1][1] = t[3];
                ldsm_x4(t, smem_u32(&Bs[1][row][k16 + bc]));
                bl[2 * p][0] = t[0]; bl[2 * p][1] = t[1];
                bl[2 * p + 1][0] = t[2]; bl[2 * p + 1][1] = t[3];
            }
#pragma unroll
            for (int mt = 0; mt < 2; mt++)
#pragma unroll
                for (int nt = 0; nt < 4; nt++) {
                    mma16816(acc[mt][nt], ah[mt], bh[nt]);
                    mma16816(acc[mt][nt], ah[mt], bl[nt]);
                    mma16816(acc[mt][nt], al[mt], bh[nt]);
                }
        }
        __syncthreads();
    }

    // ---- epilogue: bias add, fp32 store ----
    const int g  = lane >> 2;          // row group 0..7
    const int tq = lane & 3;           // col quad
#pragma unroll
    for (int mt = 0; mt < 2; mt++) {
        int row = m0 + wm * 32 + mt * 16 + g;
#pragma unroll
        for (int nt = 0; nt < 4; nt++) {
            int col = n0 + wn * 32 + nt * 8 + tq * 2;
            float bx = bias[col], by = bias[col + 1];
            float2 v0 = make_float2(acc[mt][nt][0] + bx, acc[mt][nt][1] + by);
            float2 v1 = make_float2(acc[mt][nt][2] + bx, acc[mt][nt][3] + by);
            *reinterpret_cast<float2*>(&Cout[(size_t)row * Ndim + col]) = v0;
            *reinterpret_cast<float2*>(&Cout[(size_t)(row + 8) * Ndim + col]) = v1;
        }
    }
}

// ------------------------- BN1+GELU apply + split for GEMM2 A --------------
__global__ void __launch_bounds__(256)
convert_a2_kernel(const float* __restrict__ h1, const float2* __restrict__ aff,
                  __nv_bfloat16* __restrict__ hi, __nv_bfloat16* __restrict__ lo) {
    int idx = blockIdx.x * 256 + threadIdx.x;       // one float4 per thread
    float4 v = reinterpret_cast<const float4*>(h1)[idx];
    int c0 = (idx % (C2c / 4)) * 4;
    float2 a0 = aff[c0 + 0], a1 = aff[c0 + 1], a2 = aff[c0 + 2], a3 = aff[c0 + 3];
    float g0 = gelu_exact(fmaf(v.x, a0.x, a0.y));
    float g1 = gelu_exact(fmaf(v.y, a1.x, a1.y));
    float g2 = gelu_exact(fmaf(v.z, a2.x, a2.y));
    float g3 = gelu_exact(fmaf(v.w, a3.x, a3.y));
    __nv_bfloat16 h0, l0, h1b, l1, h2b, l2, h3, l3;
    split_bf16(g0, h0, l0); split_bf16(g1, h1b, l1);
    split_bf16(g2, h2b, l2); split_bf16(g3, h3, l3);
    __nv_bfloat162 ph0; ph0.x = h0;  ph0.y = h1b;
    __nv_bfloat162 ph1; ph1.x = h2b; ph1.y = h3;
    __nv_bfloat162 pl0; pl0.x = l0;  pl0.y = l1;
    __nv_bfloat162 pl1; pl1.x = l2;  pl1.y = l3;
    uint2 uh, ul;
    uh.x = *reinterpret_cast<uint32_t*>(&ph0); uh.y = *reinterpret_cast<uint32_t*>(&ph1);
    ul.x = *reinterpret_cast<uint32_t*>(&pl0); ul.y = *reinterpret_cast<uint32_t*>(&pl1);
    reinterpret_cast<uint2*>(hi)[idx] = uh;
    reinterpret_cast<uint2*>(lo)[idx] = ul;
}

// ------------------------- deterministic BN batch stats --------------------
__global__ void stats_partial_kernel(const float* __restrict__ H, int ncols,
                                     int rowsPerBlk,
                                     float* __restrict__ ps, float* __restrict__ pq) {
    int c = threadIdx.x;
    size_t base = (size_t)blockIdx.x * rowsPerBlk;
    float s = 0.0f, q = 0.0f;
    for (int i = 0; i < rowsPerBlk; i++) {
        float v = H[(base + i) * ncols + c];
        s += v;
        q = fmaf(v, v, q);
    }
    ps[blockIdx.x * ncols + c] = s;
    pq[blockIdx.x * ncols + c] = q;
}

__global__ void stats_finalize_kernel(const float* __restrict__ ps,
                                      const float* __restrict__ pq, int ncols,
                                      const float* __restrict__ gamma,
                                      const float* __restrict__ beta,
                                      float2* __restrict__ aff) {
    int c = threadIdx.x;
    float s = 0.0f, q = 0.0f;
    for (int i = 0; i < PARTS; i++) {
        s += ps[i * ncols + c];
        q += pq[i * ncols + c];
    }
    const float inv = 1.0f / (float)Mrows;
    float mean = s * inv;
    float var  = q * inv - mean * mean;
    float sc   = gamma[c] * rsqrtf(var + EPSf);
    aff[c] = make_float2(sc, beta[c] - mean * sc);
}

// ------------------------- final BN+GELU + NHWC->NCHW ----------------------
__global__ void epilogue_kernel(const float* __restrict__ h2,
                                const float2* __restrict__ aff,
                                float* __restrict__ out) {
    __shared__ float tile[32][33];
    int b  = blockIdx.z;
    int n0 = blockIdx.x * 32;
    int o0 = blockIdx.y * 32;
    int tx = threadIdx.x, ty = threadIdx.y;
    float v  = h2[((size_t)b * Nn + n0 + ty) * OUTc + o0 + tx];
    float2 a = aff[o0 + tx];
    tile[ty][tx] = gelu_exact(fmaf(v, a.x, a.y));
    __syncthreads();
    out[((size_t)b * OUTc + o0 + ty) * Nn + n0 + tx] = tile[tx][ty];
}

// ------------------------- host driver -------------------------------------
extern "C" void kernel_launch(void* const* d_in, const int* in_sizes, int n_in,
                              void* d_out, int out_size) {
    const float* x    = (const float*)d_in[0];
    const int*   edge = (const int*)  d_in[1];
    const float* w1   = (const float*)d_in[2];
    const float* b1   = (const float*)d_in[3];
    const float* g1   = (const float*)d_in[4];
    const float* be1  = (const float*)d_in[5];
    const float* w2   = (const float*)d_in[6];
    const float* b2   = (const float*)d_in[7];
    const float* g2   = (const float*)d_in[8];
    const float* be2  = (const float*)d_in[9];
    float* out = (float*)d_out;

    float *xt, *h1, *h2, *ps, *pq;
    __nv_bfloat16 *a1hi, *a1lo, *a2hi, *a2lo, *w1hi, *w1lo, *w2hi, *w2lo;
    float2 *aff1, *aff2;
    cudaGetSymbolAddress((void**)&xt,   g_xt);
    cudaGetSymbolAddress((void**)&a1hi, g_a1hi);
    cudaGetSymbolAddress((void**)&a1lo, g_a1lo);
    cudaGetSymbolAddress((void**)&a2hi, g_a2hi);
    cudaGetSymbolAddress((void**)&a2lo, g_a2lo);
    cudaGetSymbolAddress((void**)&w1hi, g_w1hi);
    cudaGetSymbolAddress((void**)&w1lo, g_w1lo);
    cudaGetSymbolAddress((void**)&w2hi, g_w2hi);
    cudaGetSymbolAddress((void**)&w2lo, g_w2lo);
    cudaGetSymbolAddress((void**)&h1,   g_h1);
    cudaGetSymbolAddress((void**)&h2,   g_h2);
    cudaGetSymbolAddress((void**)&ps,   g_ps);
    cudaGetSymbolAddress((void**)&pq,   g_pq);
    cudaGetSymbolAddress((void**)&aff1, g_aff1);
    cudaGetSymbolAddress((void**)&aff2, g_aff2);

    dim3 blk32(32, 32);

    // 1) layout prep + weight splits
    transpose_x_kernel<<<dim3(Nn / 32, Cc / 32, Bn), blk32>>>(x, xt);
    split_w_kernel<<<(C2c * C2c + 255) / 256, 256>>>(w1, w1hi, w1lo, C2c * C2c);
    split_w_kernel<<<(OUTc * C2c + 255) / 256, 256>>>(w2, w2hi, w2lo, OUTc * C2c);

    // 2) gather + diff-max + interleave, split to bf16 hi/lo
    gather_kernel<<<Mrows / 8, 256>>>(xt, edge, a1hi, a1lo);

    // 3) GEMM1 (mma.sync bf16 x3): [25088,384] x [384,384]^T + b1 -> h1
    mma_gemm_kernel<<<dim3(C2c / GBN, Mrows / GBM), 256>>>(
        a1hi, a1lo, w1hi, w1lo, b1, h1, C2c);

    // 4) BN1 stats (deterministic two-level)
    stats_partial_kernel<<<PARTS, C2c>>>(h1, C2c, Mrows / PARTS, ps, pq);
    stats_finalize_kernel<<<1, C2c>>>(ps, pq, C2c, g1, be1, aff1);

    // 5) BN1+GELU apply + split -> GEMM2 A operand
    convert_a2_kernel<<<(Mrows * C2c / 4) / 256, 256>>>(h1, aff1, a2hi, a2lo);

    // 6) GEMM2 (mma.sync bf16 x3): [25088,384] x [192,384]^T + b2 -> h2
    mma_gemm_kernel<<<dim3(OUTc / GBN, Mrows / GBM), 256>>>(
        a2hi, a2lo, w2hi, w2lo, b2, h2, OUTc);

    // 7) BN2 stats
    stats_partial_kernel<<<PARTS, OUTc>>>(h2, OUTc, Mrows / PARTS, ps, pq);
    stats_finalize_kernel<<<1, OUTc>>>(ps, pq, OUTc, g2, be2, aff2);

    // 8) final BN+GELU + transpose to [B, OUT, H, W]
    epilogue_kernel<<<dim3(Nn / 32, OUTc / 32, Bn), blk32>>>(h2, aff2, out);
}

// round 7
// speedup vs baseline: 1.5963x; 1.0443x over previous
#include <cuda_runtime.h>
#include <cuda_bf16.h>
#include <cstdint>
#include <math.h>

// Problem constants
#define Bn   8
#define Cc   192
#define Nn   3136          // H*W
#define Kk   9
#define C2c  384           // 2*C
#define OUTc 192
#define Mrows 25088        // B*N
#define EPSf 1e-5f
#define PARTS 256

// ------------------------- device scratch ----------------------------------
__device__ __align__(16) float          g_xt[Bn * Nn * Cc];
__device__ __align__(16) __nv_bfloat16  g_a1hi[(size_t)Mrows * C2c];
__device__ __align__(16) __nv_bfloat16  g_a1lo[(size_t)Mrows * C2c];
__device__ __align__(16) __nv_bfloat16  g_a2hi[(size_t)Mrows * C2c];
__device__ __align__(16) __nv_bfloat16  g_a2lo[(size_t)Mrows * C2c];
__device__ __align__(16) __nv_bfloat16  g_w1hi[C2c * C2c];
__device__ __align__(16) __nv_bfloat16  g_w1lo[C2c * C2c];
__device__ __align__(16) __nv_bfloat16  g_w2hi[OUTc * C2c];
__device__ __align__(16) __nv_bfloat16  g_w2lo[OUTc * C2c];
__device__ __align__(16) float          g_h1[(size_t)Mrows * C2c];
__device__ __align__(16) float          g_h2[(size_t)Mrows * OUTc];
__device__ float  g_ps[PARTS * C2c];
__device__ float  g_pq[PARTS * C2c];
__device__ float2 g_aff1[C2c];
__device__ float2 g_aff2[OUTc];

__device__ __forceinline__ float gelu_exact(float x) {
    return 0.5f * x * (1.0f + erff(x * 0.70710678118654752f));
}
__device__ __forceinline__ void split_bf16(float v, __nv_bfloat16& hi, __nv_bfloat16& lo) {
    hi = __float2bfloat16(v);
    lo = __float2bfloat16(v - __bfloat162float(hi));
}
__device__ __forceinline__ uint32_t smem_u32(const void* p) {
    return (uint32_t)__cvta_generic_to_shared(p);
}
__device__ __forceinline__ void ldsm_x4(uint32_t* r, uint32_t addr) {
    asm volatile("ldmatrix.sync.aligned.m8n8.x4.shared.b16 {%0,%1,%2,%3}, [%4];"
                 : "=r"(r[0]), "=r"(r[1]), "=r"(r[2]), "=r"(r[3]) : "r"(addr));
}
__device__ __forceinline__ void mma16816(float* c, const uint32_t* a, const uint32_t* b) {
    asm volatile(
        "mma.sync.aligned.m16n8k16.row.col.f32.bf16.bf16.f32 "
        "{%0,%1,%2,%3}, {%4,%5,%6,%7}, {%8,%9}, {%0,%1,%2,%3};"
        : "+f"(c[0]), "+f"(c[1]), "+f"(c[2]), "+f"(c[3])
        : "r"(a[0]), "r"(a[1]), "r"(a[2]), "r"(a[3]), "r"(b[0]), "r"(b[1]));
}
#define CP16(dst, src)  asm volatile("cp.async.cg.shared.global [%0], [%1], 16;" :: "r"(dst), "l"(src))
#define CP_COMMIT()     asm volatile("cp.async.commit_group;" ::: "memory")
#define CP_WAIT1()      asm volatile("cp.async.wait_group 1;" ::: "memory")
#define CP_WAIT0()      asm volatile("cp.async.wait_group 0;" ::: "memory")

// ------------------------- transpose x -------------------------------------
__global__ void transpose_x_kernel(const float* __restrict__ x, float* __restrict__ xt) {
    __shared__ float tile[32][33];
    int b  = blockIdx.z;
    int n0 = blockIdx.x * 32;
    int c0 = blockIdx.y * 32;
    int tx = threadIdx.x, ty = threadIdx.y;
    tile[ty][tx] = x[((size_t)b * Cc + c0 + ty) * Nn + n0 + tx];
    __syncthreads();
    xt[((size_t)b * Nn + n0 + ty) * Cc + c0 + tx] = tile[tx][ty];
}

// ------------------------- weight split ------------------------------------
__global__ void split_w_kernel(const float* __restrict__ w, __nv_bfloat16* __restrict__ hi,
                               __nv_bfloat16* __restrict__ lo, int n) {
    int i = blockIdx.x * 256 + threadIdx.x;
    if (i < n) split_bf16(w[i], hi[i], lo[i]);
}

// ------------------------- gather + diff-max + interleave + split ----------
__global__ void __launch_bounds__(256)
gather_kernel(const float* __restrict__ xt, const int* __restrict__ edge,
              __nv_bfloat16* __restrict__ ahi, __nv_bfloat16* __restrict__ alo) {
    int warp = (blockIdx.x * blockDim.x + threadIdx.x) >> 5;
    int lane = threadIdx.x & 31;
    int b = warp / Nn;
    int n = warp % Nn;
    const float* xb = xt + (size_t)b * Nn * Cc;

    float xv[6], mv[6];
#pragma unroll
    for (int j = 0; j < 6; j++) {
        xv[j] = xb[(size_t)n * Cc + lane + 32 * j];
        mv[j] = -3.402823466e38f;
    }
    const int* e0 = edge + ((size_t)b * Nn + n) * Kk;
    const int* e1 = e0 + (size_t)Bn * Nn * Kk;
#pragma unroll
    for (int k = 0; k < Kk; k++) {
        int jn  = __ldg(&e0[k]);
        int in_ = __ldg(&e1[k]);
        const float* rj = xb + (size_t)jn  * Cc;
        const float* ri = xb + (size_t)in_ * Cc;
#pragma unroll
        for (int j = 0; j < 6; j++) {
            int c = lane + 32 * j;
            mv[j] = fmaxf(mv[j], __ldg(&rj[c]) - __ldg(&ri[c]));
        }
    }
    __nv_bfloat162* oh = reinterpret_cast<__nv_bfloat162*>(ahi + (size_t)warp * C2c);
    __nv_bfloat162* ol = reinterpret_cast<__nv_bfloat162*>(alo + (size_t)warp * C2c);
#pragma unroll
    for (int j = 0; j < 6; j++) {
        __nv_bfloat16 xh, xl, mh, ml;
        split_bf16(xv[j], xh, xl);
        split_bf16(mv[j], mh, ml);
        __nv_bfloat162 vh; vh.x = xh; vh.y = mh;
        __nv_bfloat162 vl; vl.x = xl; vl.y = ml;
        oh[lane + 32 * j] = vh;
        ol[lane + 32 * j] = vl;
    }
}

// ------------------------- pipelined mma.sync split-bf16 GEMM --------------
// C[M,Ndim] = A[M,384] * B[Ndim,384]^T + bias, 3-term bf16 split.
// BM=128, K-chunks of 32, 2-stage cp.async double buffer.
// 8 warps in WGM x WGN grid; warp tile (WMT*16) x (WNT*8).
#define GBK  32
#define LDAe 40              // bf16 elems per smem row (32 + 8 pad)

template <int BN, int WGM, int WGN, int WMT, int WNT, int MINB>
__global__ void __launch_bounds__(256, MINB)
mma_gemm_pipe(const __nv_bfloat16* __restrict__ Ahi, const __nv_bfloat16* __restrict__ Alo,
              const __nv_bfloat16* __restrict__ Bhi, const __nv_bfloat16* __restrict__ Blo,
              const float* __restrict__ bias, float* __restrict__ Cout, int Ndim) {
    static_assert(WGM * WGN == 8 && WGM * WMT * 16 == 128 && WGN * WNT * 8 == BN, "cfg");
    extern __shared__ __align__(16) char smem[];
    constexpr int AHALF = 128 * LDAe * 2;      // bytes per A half (hi or lo)
    constexpr int BHALF = BN  * LDAe * 2;
    constexpr int STAGE = 2 * AHALF + 2 * BHALF;

    const int tid  = threadIdx.x;
    const int wid  = tid >> 5;
    const int lane = tid & 31;
    const int wm   = wid / WGN;
    const int wn   = wid % WGN;
    const int m0   = blockIdx.y * 128;
    const int n0   = blockIdx.x * BN;
    const uint32_t sb = smem_u32(smem);

    float acc[WMT][WNT][4];
#pragma unroll
    for (int i = 0; i < WMT; i++)
#pragma unroll
        for (int j = 0; j < WNT; j++)
#pragma unroll
            for (int q = 0; q < 4; q++) acc[i][j][q] = 0.0f;

    // ldmatrix lane coords
    const int ar = lane & 15;
    const int ac = (lane >> 4) << 3;
    const int br = (lane & 7) + ((lane >> 4) << 3);
    const int bc = ((lane >> 3) & 1) << 3;

    auto load_stage = [&](int stg, int kb) {
        const uint32_t a_hi = sb + stg * STAGE;
        const uint32_t a_lo = a_hi + AHALF;
        const uint32_t b_hi = a_hi + 2 * AHALF;
        const uint32_t b_lo = b_hi + BHALF;
#pragma unroll
        for (int i = 0; i < 2; i++) {                       // A: 512 slots
            int idx = tid + 256 * i;
            int row = idx >> 2, c8 = (idx & 3) << 3;
            size_t  go = (size_t)(m0 + row) * C2c + kb + c8;
            uint32_t so = (uint32_t)(row * LDAe + c8) * 2;
            CP16(a_hi + so, Ahi + go);
            CP16(a_lo + so, Alo + go);
        }
#pragma unroll
        for (int i = 0; i < BN * 4 / 256; i++) {            // B: BN*4 slots
            int idx = tid + 256 * i;
            int row = idx >> 2, c8 = (idx & 3) << 3;
            size_t  go = (size_t)(n0 + row) * C2c + kb + c8;
            uint32_t so = (uint32_t)(row * LDAe + c8) * 2;
            CP16(b_hi + so, Bhi + go);
            CP16(b_lo + so, Blo + go);
        }
        CP_COMMIT();
    };

    load_stage(0, 0);

    constexpr int KITERS = C2c / GBK;      // 12
    for (int it = 0; it < KITERS; it++) {
        if (it + 1 < KITERS) {
            load_stage((it + 1) & 1, (it + 1) * GBK);
            CP_WAIT1();
        } else {
            CP_WAIT0();
        }
        __syncthreads();

        const int stg = it & 1;
        const uint32_t a_hi = sb + stg * STAGE;
        const uint32_t a_lo = a_hi + AHALF;
        const uint32_t b_hi = a_hi + 2 * AHALF;
        const uint32_t b_lo = b_hi + BHALF;

#pragma unroll
        for (int ks = 0; ks < 2; ks++) {
            const int k16 = ks * 16;
            uint32_t ah[WMT][4], al[WMT][4];
#pragma unroll
            for (int mt = 0; mt < WMT; mt++) {
                int row = wm * WMT * 16 + mt * 16 + ar;
                uint32_t off = (uint32_t)(row * LDAe + k16 + ac) * 2;
                ldsm_x4(ah[mt], a_hi + off);
                ldsm_x4(al[mt], a_lo + off);
            }
            uint32_t bh[WNT][2], bl[WNT][2];
#pragma unroll
            for (int p = 0; p < WNT / 2; p++) {
                int row = wn * WNT * 8 + p * 16 + br;
                uint32_t off = (uint32_t)(row * LDAe + k16 + bc) * 2;
                uint32_t t[4];
                ldsm_x4(t, b_hi + off);
                bh[2 * p][0] = t[0]; bh[2 * p][1] = t[1];
                bh[2 * p + 1][0] = t[2]; bh[2 * p + 1][1] = t[3];
                ldsm_x4(t, b_lo + off);
                bl[2 * p][0] = t[0]; bl[2 * p][1] = t[1];
                bl[2 * p + 1][0] = t[2]; bl[2 * p + 1][1] = t[3];
            }
#pragma unroll
            for (int mt = 0; mt < WMT; mt++)
#pragma unroll
                for (int nt = 0; nt < WNT; nt++) {
                    mma16816(acc[mt][nt], ah[mt], bh[nt]);
                    mma16816(acc[mt][nt], ah[mt], bl[nt]);
                    mma16816(acc[mt][nt], al[mt], bh[nt]);
                }
        }
        __syncthreads();
    }

    // epilogue: bias add, fp32 store
    const int g  = lane >> 2;
    const int tq = lane & 3;
#pragma unroll
    for (int mt = 0; mt < WMT; mt++) {
        int row = m0 + wm * WMT * 16 + mt * 16 + g;
#pragma unroll
        for (int nt = 0; nt < WNT; nt++) {
            int col = n0 + wn * WNT * 8 + nt * 8 + tq * 2;
            float bx = bias[col], by = bias[col + 1];
            float2 v0 = make_float2(acc[mt][nt][0] + bx, acc[mt][nt][1] + by);
            float2 v1 = make_float2(acc[mt][nt][2] + bx, acc[mt][nt][3] + by);
            *reinterpret_cast<float2*>(&Cout[(size_t)row * Ndim + col]) = v0;
            *reinterpret_cast<float2*>(&Cout[(size_t)(row + 8) * Ndim + col]) = v1;
        }
    }
}

// ------------------------- BN1+GELU apply + split for GEMM2 A --------------
__global__ void __launch_bounds__(256)
convert_a2_kernel(const float* __restrict__ h1, const float2* __restrict__ aff,
                  __nv_bfloat16* __restrict__ hi, __nv_bfloat16* __restrict__ lo) {
    int idx = blockIdx.x * 256 + threadIdx.x;
    float4 v = reinterpret_cast<const float4*>(h1)[idx];
    int c0 = (idx % (C2c / 4)) * 4;
    float2 a0 = aff[c0 + 0], a1 = aff[c0 + 1], a2 = aff[c0 + 2], a3 = aff[c0 + 3];
    float g0 = gelu_exact(fmaf(v.x, a0.x, a0.y));
    float g1 = gelu_exact(fmaf(v.y, a1.x, a1.y));
    float g2 = gelu_exact(fmaf(v.z, a2.x, a2.y));
    float g3 = gelu_exact(fmaf(v.w, a3.x, a3.y));
    __nv_bfloat16 h0, l0, h1b, l1, h2b, l2, h3, l3;
    split_bf16(g0, h0, l0); split_bf16(g1, h1b, l1);
    split_bf16(g2, h2b, l2); split_bf16(g3, h3, l3);
    __nv_bfloat162 ph0; ph0.x = h0;  ph0.y = h1b;
    __nv_bfloat162 ph1; ph1.x = h2b; ph1.y = h3;
    __nv_bfloat162 pl0; pl0.x = l0;  pl0.y = l1;
    __nv_bfloat162 pl1; pl1.x = l2;  pl1.y = l3;
    uint2 uh, ul;
    uh.x = *reinterpret_cast<uint32_t*>(&ph0); uh.y = *reinterpret_cast<uint32_t*>(&ph1);
    ul.x = *reinterpret_cast<uint32_t*>(&pl0); ul.y = *reinterpret_cast<uint32_t*>(&pl1);
    reinterpret_cast<uint2*>(hi)[idx] = uh;
    reinterpret_cast<uint2*>(lo)[idx] = ul;
}

// ------------------------- deterministic BN batch stats --------------------
__global__ void stats_partial_kernel(const float* __restrict__ H, int ncols,
                                     int rowsPerBlk,
                                     float* __restrict__ ps, float* __restrict__ pq) {
    int c = threadIdx.x;
    size_t base = (size_t)blockIdx.x * rowsPerBlk;
    float s = 0.0f, q = 0.0f;
    for (int i = 0; i < rowsPerBlk; i++) {
        float v = H[(base + i) * ncols + c];
        s += v;
        q = fmaf(v, v, q);
    }
    ps[blockIdx.x * ncols + c] = s;
    pq[blockIdx.x * ncols + c] = q;
}

__global__ void stats_finalize_kernel(const float* __restrict__ ps,
                                      const float* __restrict__ pq, int ncols,
                                      const float* __restrict__ gamma,
                                      const float* __restrict__ beta,
                                      float2* __restrict__ aff) {
    int c = threadIdx.x;
    float s = 0.0f, q = 0.0f;
    for (int i = 0; i < PARTS; i++) {
        s += ps[i * ncols + c];
        q += pq[i * ncols + c];
    }
    const float inv = 1.0f / (float)Mrows;
    float mean = s * inv;
    float var  = q * inv - mean * mean;
    float sc   = gamma[c] * rsqrtf(var + EPSf);
    aff[c] = make_float2(sc, beta[c] - mean * sc);
}

// ------------------------- final BN+GELU + NHWC->NCHW ----------------------
__global__ void epilogue_kernel(const float* __restrict__ h2,
                                const float2* __restrict__ aff,
                                float* __restrict__ out) {
    __shared__ float tile[32][33];
    int b  = blockIdx.z;
    int n0 = blockIdx.x * 32;
    int o0 = blockIdx.y * 32;
    int tx = threadIdx.x, ty = threadIdx.y;
    float v  = h2[((size_t)b * Nn + n0 + ty) * OUTc + o0 + tx];
    float2 a = aff[o0 + tx];
    tile[ty][tx] = gelu_exact(fmaf(v, a.x, a.y));
    __syncthreads();
    out[((size_t)b * OUTc + o0 + ty) * Nn + n0 + tx] = tile[tx][ty];
}

// ------------------------- host driver -------------------------------------
extern "C" void kernel_launch(void* const* d_in, const int* in_sizes, int n_in,
                              void* d_out, int out_size) {
    const float* x    = (const float*)d_in[0];
    const int*   edge = (const int*)  d_in[1];
    const float* w1   = (const float*)d_in[2];
    const float* b1   = (const float*)d_in[3];
    const float* g1   = (const float*)d_in[4];
    const float* be1  = (const float*)d_in[5];
    const float* w2   = (const float*)d_in[6];
    const float* b2   = (const float*)d_in[7];
    const float* g2   = (const float*)d_in[8];
    const float* be2  = (const float*)d_in[9];
    float* out = (float*)d_out;

    float *xt, *h1, *h2, *ps, *pq;
    __nv_bfloat16 *a1hi, *a1lo, *a2hi, *a2lo, *w1hi, *w1lo, *w2hi, *w2lo;
    float2 *aff1, *aff2;
    cudaGetSymbolAddress((void**)&xt,   g_xt);
    cudaGetSymbolAddress((void**)&a1hi, g_a1hi);
    cudaGetSymbolAddress((void**)&a1lo, g_a1lo);
    cudaGetSymbolAddress((void**)&a2hi, g_a2hi);
    cudaGetSymbolAddress((void**)&a2lo, g_a2lo);
    cudaGetSymbolAddress((void**)&w1hi, g_w1hi);
    cudaGetSymbolAddress((void**)&w1lo, g_w1lo);
    cudaGetSymbolAddress((void**)&w2hi, g_w2hi);
    cudaGetSymbolAddress((void**)&w2lo, g_w2lo);
    cudaGetSymbolAddress((void**)&h1,   g_h1);
    cudaGetSymbolAddress((void**)&h2,   g_h2);
    cudaGetSymbolAddress((void**)&ps,   g_ps);
    cudaGetSymbolAddress((void**)&pq,   g_pq);
    cudaGetSymbolAddress((void**)&aff1, g_aff1);
    cudaGetSymbolAddress((void**)&aff2, g_aff2);

    // GEMM1: BN=128, warp grid 2x4, warp tile 64x32.  smem = 2*(2*10240+2*10240)
    constexpr int SMEM1 = 2 * (2 * 128 * LDAe * 2 + 2 * 128 * LDAe * 2); // 81920
    // GEMM2: BN=64, warp grid 4x2, warp tile 32x32.   smem = 2*(2*10240+2*5120)
    constexpr int SMEM2 = 2 * (2 * 128 * LDAe * 2 + 2 * 64 * LDAe * 2);  // 61440
    cudaFuncSetAttribute((const void*)mma_gemm_pipe<128, 2, 4, 4, 4, 1>,
                         cudaFuncAttributeMaxDynamicSharedMemorySize, SMEM1);
    cudaFuncSetAttribute((const void*)mma_gemm_pipe<64, 4, 2, 2, 4, 2>,
                         cudaFuncAttributeMaxDynamicSharedMemorySize, SMEM2);

    dim3 blk32(32, 32);

    // 1) layout prep + weight splits
    transpose_x_kernel<<<dim3(Nn / 32, Cc / 32, Bn), blk32>>>(x, xt);
    split_w_kernel<<<(C2c * C2c + 255) / 256, 256>>>(w1, w1hi, w1lo, C2c * C2c);
    split_w_kernel<<<(OUTc * C2c + 255) / 256, 256>>>(w2, w2hi, w2lo, OUTc * C2c);

    // 2) gather + diff-max + interleave, split to bf16 hi/lo
    gather_kernel<<<Mrows / 8, 256>>>(xt, edge, a1hi, a1lo);

    // 3) GEMM1 (pipelined): [25088,384] x [384,384]^T + b1 -> h1
    mma_gemm_pipe<128, 2, 4, 4, 4, 1>
        <<<dim3(C2c / 128, Mrows / 128), 256, SMEM1>>>(
            a1hi, a1lo, w1hi, w1lo, b1, h1, C2c);

    // 4) BN1 stats (deterministic two-level)
    stats_partial_kernel<<<PARTS, C2c>>>(h1, C2c, Mrows / PARTS, ps, pq);
    stats_finalize_kernel<<<1, C2c>>>(ps, pq, C2c, g1, be1, aff1);

    // 5) BN1+GELU apply + split -> GEMM2 A operand
    convert_a2_kernel<<<(Mrows * C2c / 4) / 256, 256>>>(h1, aff1, a2hi, a2lo);

    // 6) GEMM2 (pipelined): [25088,384] x [192,384]^T + b2 -> h2
    mma_gemm_pipe<64, 4, 2, 2, 4, 2>
        <<<dim3(OUTc / 64, Mrows / 128), 256, SMEM2>>>(
            a2hi, a2lo, w2hi, w2lo, b2, h2, OUTc);

    // 7) BN2 stats
    stats_partial_kernel<<<PARTS, OUTc>>>(h2, OUTc, Mrows / PARTS, ps, pq);
    stats_finalize_kernel<<<1, OUTc>>>(ps, pq, OUTc, g2, be2, aff2);

    // 8) final BN+GELU + transpose to [B, OUT, H, W]
    epilogue_kernel<<<dim3(Nn / 32, OUTc / 32, Bn), blk32>>>(h2, aff2, out);
}